// round 1
// baseline (speedup 1.0000x reference)
#include <cuda_runtime.h>
#include <math.h>

#define BATCH 8
#define P0    4608
#define CDIM  1024
#define HEADS 16
#define DDIM  64
#define HDIM  4096
#define NMAX  2304
#define TOUT  128

// ---------------- scratch (static device arrays; no allocation) ----------------
__device__ float g_bufA[(size_t)BATCH * P0   * CDIM];   // 151 MB
__device__ float g_bufB[(size_t)BATCH * NMAX * CDIM];   // 75.5 MB
__device__ float g_sizeA[BATCH * P0];
__device__ float g_sizeB[BATCH * NMAX];
__device__ float g_metric[(size_t)BATCH * P0 * DDIM];   // 9.4 MB
__device__ float g_nodemax[BATCH * NMAX];
__device__ int   g_nodeidx[BATCH * NMAX];
__device__ int   g_edge[BATCH * 72];
__device__ float g_h[(size_t)BATCH * TOUT * HDIM];      // 16 MB

// ---------------- metric: head-mean + L2 normalize ----------------
// one block (64 threads) per token; ws is (B, p, C); pos optional (round 1)
__global__ void k_metric(const float* __restrict__ ws, const float* __restrict__ pos,
                         float* __restrict__ metric, int p)
{
    int t   = blockIdx.x;        // 0 .. B*p-1
    int tok = t % p;
    const float* base = ws + (size_t)t * CDIM;
    int d = threadIdx.x;         // 0..63
    float s = 0.f;
    if (pos) {
        const float* pb = pos + (size_t)tok * CDIM;
        #pragma unroll
        for (int h = 0; h < HEADS; ++h) s += base[h * DDIM + d] + pb[h * DDIM + d];
    } else {
        #pragma unroll
        for (int h = 0; h < HEADS; ++h) s += base[h * DDIM + d];
    }
    float m = s * (1.f / 16.f);
    __shared__ float red[64];
    red[d] = m * m;
    __syncthreads();
    for (int off = 32; off > 0; off >>= 1) {
        if (d < off) red[d] += red[d + off];
        __syncthreads();
    }
    float nrm = sqrtf(red[0]);
    metric[(size_t)t * DDIM + d] = m / nrm;
}

// ---------------- fused scores + row argmax ----------------
// A_i = metric[2i], B_j = metric[2j+1]; per i: max_j dot(A_i, B_j) (first-max tie-break)
// 32 i-rows per block, 128 j per tile, 4x4 register tile per thread.
__global__ __launch_bounds__(256) void k_argmax(const float* __restrict__ metric,
        float* __restrict__ nodemax, int* __restrict__ nodeidx, int n, int p)
{
    __shared__ float As[32][65];
    __shared__ float Bs[128][65];
    __shared__ float rv[32][33];
    __shared__ int   ri[32][33];

    int b     = blockIdx.y;
    int ibase = blockIdx.x * 32;
    const float* M = metric + (size_t)b * p * DDIM;
    int tid = threadIdx.x;
    int tx  = tid & 7;        // i group: rows 4*tx..4*tx+3
    int ty  = tid >> 3;       // j group: cols 4*ty..4*ty+3 (0..31)

    for (int idx = tid; idx < 32 * 64; idx += 256) {
        int r = idx >> 6, c = idx & 63;
        int ig = ibase + r;
        As[r][c] = (ig < n) ? M[(size_t)(2 * ig) * DDIM + c] : 0.f;
    }

    float runv = -1e30f;  // running best for i = ibase + tid (tid < 32 only)
    int   runj = 0;

    int ntiles = (n + 127) >> 7;
    for (int jt = 0; jt < ntiles; ++jt) {
        int jbase = jt << 7;
        __syncthreads();
        for (int idx = tid; idx < 128 * 64; idx += 256) {
            int r = idx >> 6, c = idx & 63;
            int jg = jbase + r;
            Bs[r][c] = (jg < n) ? M[(size_t)(2 * jg + 1) * DDIM + c] : 0.f;
        }
        __syncthreads();

        float acc[4][4];
        #pragma unroll
        for (int ii = 0; ii < 4; ii++)
            #pragma unroll
            for (int jj = 0; jj < 4; jj++) acc[ii][jj] = 0.f;

        #pragma unroll 8
        for (int k = 0; k < 64; k++) {
            float a0 = As[4 * tx + 0][k], a1 = As[4 * tx + 1][k];
            float a2 = As[4 * tx + 2][k], a3 = As[4 * tx + 3][k];
            float b0 = Bs[4 * ty + 0][k], b1 = Bs[4 * ty + 1][k];
            float b2 = Bs[4 * ty + 2][k], b3 = Bs[4 * ty + 3][k];
            acc[0][0] += a0 * b0; acc[0][1] += a0 * b1; acc[0][2] += a0 * b2; acc[0][3] += a0 * b3;
            acc[1][0] += a1 * b0; acc[1][1] += a1 * b1; acc[1][2] += a1 * b2; acc[1][3] += a1 * b3;
            acc[2][0] += a2 * b0; acc[2][1] += a2 * b1; acc[2][2] += a2 * b2; acc[2][3] += a2 * b3;
            acc[3][0] += a3 * b0; acc[3][1] += a3 * b1; acc[3][2] += a3 * b2; acc[3][3] += a3 * b3;
        }

        // per-thread fold over its 4 j's (ascending j, strict > => first max)
        #pragma unroll
        for (int ii = 0; ii < 4; ii++) {
            float bv = -1e30f; int bj = -1;
            #pragma unroll
            for (int jj = 0; jj < 4; jj++) {
                int jg = jbase + 4 * ty + jj;
                if (jg < n && acc[ii][jj] > bv) { bv = acc[ii][jj]; bj = jg; }
            }
            rv[4 * tx + ii][ty] = bv;
            ri[4 * tx + ii][ty] = bj;
        }
        __syncthreads();
        if (tid < 32) {
            for (int t2 = 0; t2 < 32; ++t2) {   // ascending j order
                float v = rv[tid][t2];
                if (v > runv) { runv = v; runj = ri[tid][t2]; }
            }
        }
    }
    if (tid < 32) {
        int ig = ibase + tid;
        if (ig < n) {
            nodemax[b * NMAX + ig] = runv;
            nodeidx[b * NMAX + ig] = runj;
        }
    }
}

// ---------------- rounds 1-5 merge (r == n): dst init + scatter-add ----------------
__global__ void k_dst_init(const float* __restrict__ ws, const float* __restrict__ pos,
        const float* __restrict__ szin, float* __restrict__ wsout, float* __restrict__ szout,
        int n, int p)
{
    int blk = blockIdx.x;
    int b = blk / n, j = blk % n;
    const float4* src = (const float4*)(ws + ((size_t)b * p + 2 * j + 1) * CDIM);
    float4* dst = (float4*)(wsout + ((size_t)b * n + j) * CDIM);
    int c = threadIdx.x;  // 256 threads * float4 = 1024
    float4 v = src[c];
    if (pos) {
        const float4* pb = (const float4*)(pos + (size_t)(2 * j + 1) * CDIM);
        float4 pv = pb[c];
        v.x += pv.x; v.y += pv.y; v.z += pv.z; v.w += pv.w;
    }
    dst[c] = v;
    if (threadIdx.x == 0) szout[b * n + j] = szin ? szin[b * p + 2 * j + 1] : 1.f;
}

__global__ void k_scatter(const float* __restrict__ ws, const float* __restrict__ pos,
        const float* __restrict__ szin, const int* __restrict__ nodeidx,
        float* __restrict__ wsout, float* __restrict__ szout, int n, int p)
{
    int blk = blockIdx.x;
    int b = blk / n, i = blk % n;
    int j = nodeidx[b * NMAX + i];
    const float* src = ws + ((size_t)b * p + 2 * i) * CDIM;
    float* dst = wsout + ((size_t)b * n + j) * CDIM;
    if (pos) {
        const float* pb = pos + (size_t)(2 * i) * CDIM;
        for (int c = threadIdx.x; c < CDIM; c += 256) atomicAdd(dst + c, src[c] + pb[c]);
    } else {
        for (int c = threadIdx.x; c < CDIM; c += 256) atomicAdd(dst + c, src[c]);
    }
    if (threadIdx.x == 0) atomicAdd(szout + b * n + j, szin ? szin[b * p + 2 * i] : 1.f);
}

// ---------------- round 6: stable descending sort of 72 node_max, then merge ----------------
__global__ void k_sort6(const float* __restrict__ nodemax, int* __restrict__ edge)
{
    if (threadIdx.x != 0) return;
    int b = blockIdx.x;
    float v[72]; int id[72];
    for (int i = 0; i < 72; i++) { v[i] = nodemax[b * NMAX + i]; id[i] = i; }
    for (int a = 1; a < 72; a++) {            // stable insertion sort, descending
        float kv = v[a]; int ki = id[a]; int c = a - 1;
        while (c >= 0 && v[c] < kv) { v[c + 1] = v[c]; id[c + 1] = id[c]; --c; }
        v[c + 1] = kv; id[c + 1] = ki;
    }
    for (int i = 0; i < 72; i++) edge[b * 72 + i] = id[i];
}

__global__ void k_round6(const float* __restrict__ ws, const float* __restrict__ sz,
        const int* __restrict__ nodeidx, const int* __restrict__ edge,
        float* __restrict__ wsout, float* __restrict__ szout)
{
    const int p = 144, r = 16, u = 56;
    int b = blockIdx.y, t = blockIdx.x;   // t < 128
    const float* wsb = ws + (size_t)b * p * CDIM;
    float* outp = wsout + ((size_t)b * 128 + t) * CDIM;
    if (t < u) {
        int e = edge[b * 72 + r + t];
        const float* src = wsb + (size_t)(2 * e) * CDIM;
        for (int c = threadIdx.x; c < CDIM; c += 256) outp[c] = src[c];
        if (threadIdx.x == 0) szout[b * 128 + t] = sz[b * p + 2 * e];
    } else {
        int j = t - u;
        __shared__ int msrc[16];
        __shared__ int mcount;
        if (threadIdx.x == 0) {
            int cnt = 0;
            float ssum = sz[b * p + 2 * j + 1];
            for (int s = 0; s < r; s++) {
                int e = edge[b * 72 + s];
                if (nodeidx[b * NMAX + e] == j) { msrc[cnt++] = 2 * e; ssum += sz[b * p + 2 * e]; }
            }
            mcount = cnt;
            szout[b * 128 + t] = ssum;
        }
        __syncthreads();
        const float* base = wsb + (size_t)(2 * j + 1) * CDIM;
        int cnt = mcount;
        for (int c = threadIdx.x; c < CDIM; c += 256) {
            float v = base[c];
            for (int q = 0; q < cnt; q++) v += wsb[(size_t)msrc[q] * CDIM + c];
            outp[c] = v;
        }
    }
}

// ---------------- fp32 GEMM: Out = act(A(/size) @ Wt + bias) ----------------
// A (M,K) row-major, Wt (K,N) row-major. 128x128 tile, BK=8, 8x8 per thread.
template<bool GELU>
__global__ __launch_bounds__(256) void k_gemm(const float* __restrict__ A,
        const float* __restrict__ Wt, const float* __restrict__ bias,
        const float* __restrict__ sz, float* __restrict__ Out,
        int M, int N, int K)
{
    __shared__ float As[8][128];
    __shared__ float Bs[8][128];
    int tid = threadIdx.x;
    int tx = tid & 15, ty = tid >> 4;
    int m0 = blockIdx.y * 128, n0 = blockIdx.x * 128;

    float acc[8][8];
    #pragma unroll
    for (int i = 0; i < 8; i++)
        #pragma unroll
        for (int j = 0; j < 8; j++) acc[i][j] = 0.f;

    int arow = tid >> 1;
    int acol = (tid & 1) * 4;
    float ascale = sz ? (1.f / sz[m0 + arow]) : 1.f;
    const float* Aptr = A + (size_t)(m0 + arow) * K + acol;
    int brow = tid >> 5;
    int bcol = (tid & 31) * 4;
    const float* Bptr = Wt + (size_t)brow * N + n0 + bcol;

    for (int k0 = 0; k0 < K; k0 += 8) {
        float4 av = *(const float4*)(Aptr + k0);
        float4 bv = *(const float4*)(Bptr + (size_t)k0 * N);
        __syncthreads();
        As[acol + 0][arow] = av.x * ascale;
        As[acol + 1][arow] = av.y * ascale;
        As[acol + 2][arow] = av.z * ascale;
        As[acol + 3][arow] = av.w * ascale;
        *(float4*)&Bs[brow][bcol] = bv;
        __syncthreads();
        #pragma unroll
        for (int k = 0; k < 8; k++) {
            float af[8], bf[8];
            #pragma unroll
            for (int i = 0; i < 4; i++) { af[i] = As[k][ty * 4 + i]; af[4 + i] = As[k][64 + ty * 4 + i]; }
            #pragma unroll
            for (int j = 0; j < 4; j++) { bf[j] = Bs[k][tx * 4 + j]; bf[4 + j] = Bs[k][64 + tx * 4 + j]; }
            #pragma unroll
            for (int i = 0; i < 8; i++)
                #pragma unroll
                for (int j = 0; j < 8; j++) acc[i][j] += af[i] * bf[j];
        }
    }

    #pragma unroll
    for (int i = 0; i < 8; i++) {
        int m = m0 + ((i < 4) ? (ty * 4 + i) : (64 + ty * 4 + (i - 4)));
        #pragma unroll
        for (int j = 0; j < 8; j++) {
            int nn = n0 + ((j < 4) ? (tx * 4 + j) : (64 + tx * 4 + (j - 4)));
            float v = acc[i][j] + bias[nn];
            if (GELU) v = 0.5f * v * (1.f + erff(v * 0.70710678118654752f));
            Out[(size_t)m * N + nn] = v;
        }
    }
}

// ---------------- launcher ----------------
extern "C" void kernel_launch(void* const* d_in, const int* in_sizes, int n_in,
                              void* d_out, int out_size)
{
    const float* x   = (const float*)d_in[0];
    const float* pos = (const float*)d_in[1];
    const float* W1  = (const float*)d_in[2];
    const float* b1  = (const float*)d_in[3];
    const float* W2  = (const float*)d_in[4];
    const float* b2  = (const float*)d_in[5];
    float* out = (float*)d_out;

    float *bufA, *bufB, *szA, *szB, *metric, *nmax, *hbuf;
    int *nidx, *edge;
    cudaGetSymbolAddress((void**)&bufA,   g_bufA);
    cudaGetSymbolAddress((void**)&bufB,   g_bufB);
    cudaGetSymbolAddress((void**)&szA,    g_sizeA);
    cudaGetSymbolAddress((void**)&szB,    g_sizeB);
    cudaGetSymbolAddress((void**)&metric, g_metric);
    cudaGetSymbolAddress((void**)&nmax,   g_nodemax);
    cudaGetSymbolAddress((void**)&nidx,   g_nodeidx);
    cudaGetSymbolAddress((void**)&edge,   g_edge);
    cudaGetSymbolAddress((void**)&hbuf,   g_h);

    // Round 1: p=4608, n=r=2304, ws = x + pos, size = 1. out -> bufB/szB
    k_metric<<<BATCH * 4608, 64>>>(x, pos, metric, 4608);
    k_argmax<<<dim3(72, BATCH), 256>>>(metric, nmax, nidx, 2304, 4608);
    k_dst_init<<<BATCH * 2304, 256>>>(x, pos, nullptr, bufB, szB, 2304, 4608);
    k_scatter<<<BATCH * 2304, 256>>>(x, pos, nullptr, nidx, bufB, szB, 2304, 4608);

    // Round 2: p=2304, n=r=1152. B -> A
    k_metric<<<BATCH * 2304, 64>>>(bufB, nullptr, metric, 2304);
    k_argmax<<<dim3(36, BATCH), 256>>>(metric, nmax, nidx, 1152, 2304);
    k_dst_init<<<BATCH * 1152, 256>>>(bufB, nullptr, szB, bufA, szA, 1152, 2304);
    k_scatter<<<BATCH * 1152, 256>>>(bufB, nullptr, szB, nidx, bufA, szA, 1152, 2304);

    // Round 3: p=1152, n=r=576. A -> B
    k_metric<<<BATCH * 1152, 64>>>(bufA, nullptr, metric, 1152);
    k_argmax<<<dim3(18, BATCH), 256>>>(metric, nmax, nidx, 576, 1152);
    k_dst_init<<<BATCH * 576, 256>>>(bufA, nullptr, szA, bufB, szB, 576, 1152);
    k_scatter<<<BATCH * 576, 256>>>(bufA, nullptr, szA, nidx, bufB, szB, 576, 1152);

    // Round 4: p=576, n=r=288. B -> A
    k_metric<<<BATCH * 576, 64>>>(bufB, nullptr, metric, 576);
    k_argmax<<<dim3(9, BATCH), 256>>>(metric, nmax, nidx, 288, 576);
    k_dst_init<<<BATCH * 288, 256>>>(bufB, nullptr, szB, bufA, szA, 288, 576);
    k_scatter<<<BATCH * 288, 256>>>(bufB, nullptr, szB, nidx, bufA, szA, 288, 576);

    // Round 5: p=288, n=r=144. A -> B
    k_metric<<<BATCH * 288, 64>>>(bufA, nullptr, metric, 288);
    k_argmax<<<dim3(5, BATCH), 256>>>(metric, nmax, nidx, 144, 288);
    k_dst_init<<<BATCH * 144, 256>>>(bufA, nullptr, szA, bufB, szB, 144, 288);
    k_scatter<<<BATCH * 144, 256>>>(bufA, nullptr, szA, nidx, bufB, szB, 144, 288);

    // Round 6: p=144, n=72, r=16 (needs sort). B -> A (final 128 tokens)
    k_metric<<<BATCH * 144, 64>>>(bufB, nullptr, metric, 144);
    k_argmax<<<dim3(3, BATCH), 256>>>(metric, nmax, nidx, 72, 144);
    k_sort6<<<BATCH, 32>>>(nmax, edge);
    k_round6<<<dim3(128, BATCH), 256>>>(bufB, szB, nidx, edge, bufA, szA);

    // MLP: h = gelu((ws/size) @ W1 + b1); out = h @ W2 + b2
    k_gemm<true ><<<dim3(32, 8), 256>>>(bufA, W1, b1, szA, hbuf, 1024, 4096, 1024);
    k_gemm<false><<<dim3(32, 8), 256>>>(hbuf, W2, b2, nullptr, out, 1024, 4096, 4096);
}

// round 3
// speedup vs baseline: 1.3139x; 1.3139x over previous
#include <cuda_runtime.h>
#include <cuda_bf16.h>
#include <math.h>
#include <stdint.h>

#define BATCH 8
#define P0    4608
#define CDIM  1024
#define HEADS 16
#define DDIM  64
#define HDIM  4096
#define NMAX  2304
#define TOUT  128

// ---------------- PTX helpers (sm_103 baseline ISA only) ----------------
__device__ __forceinline__ uint32_t smem_u32(const void* p) {
    uint32_t a;
    asm("{ .reg .u64 t; cvta.to.shared.u64 t, %1; cvt.u32.u64 %0, t; }" : "=r"(a) : "l"(p));
    return a;
}
__device__ __forceinline__ void ldsm4(uint32_t* r, uint32_t addr) {
    asm volatile("ldmatrix.sync.aligned.m8n8.x4.shared.b16 {%0,%1,%2,%3}, [%4];"
        : "=r"(r[0]), "=r"(r[1]), "=r"(r[2]), "=r"(r[3]) : "r"(addr));
}
__device__ __forceinline__ void mma_bf16(float* c, const uint32_t* a, uint32_t b0, uint32_t b1) {
    asm volatile("mma.sync.aligned.m16n8k16.row.col.f32.bf16.bf16.f32 "
        "{%0,%1,%2,%3}, {%4,%5,%6,%7}, {%8,%9}, {%0,%1,%2,%3};"
        : "+f"(c[0]), "+f"(c[1]), "+f"(c[2]), "+f"(c[3])
        : "r"(a[0]), "r"(a[1]), "r"(a[2]), "r"(a[3]), "r"(b0), "r"(b1));
}
#define CP_ASYNC(dst, src) asm volatile("cp.async.cg.shared.global [%0], [%1], 16;" :: "r"(dst), "l"(src))
#define CP_COMMIT()        asm volatile("cp.async.commit_group;" ::: "memory")
#define CP_WAIT(n)         asm volatile("cp.async.wait_group %0;" :: "n"(n) : "memory")

// ---------------- scratch ----------------
__device__ float g_bufA[(size_t)BATCH * 1152 * CDIM];
__device__ float g_bufB[(size_t)BATCH * NMAX * CDIM];
__device__ float g_sizeA[BATCH * 1152];
__device__ float g_sizeB[BATCH * NMAX];
__device__ float g_metric[(size_t)BATCH * P0 * DDIM];
__device__ float g_nodemax[BATCH * NMAX];
__device__ int   g_nodeidx[BATCH * NMAX];
__device__ int   g_edge[BATCH * 72];
__device__ __nv_bfloat16 g_A1[(size_t)1024 * 3072];    // GEMM1 A' [hi|lo|hi]
__device__ __nv_bfloat16 g_A2[(size_t)1024 * 12288];   // GEMM2 A' (written by GEMM1 epilogue)
__device__ __nv_bfloat16 g_W1b[(size_t)4096 * 3072];   // W1' [N,3K] [hi|hi|lo]
__device__ __nv_bfloat16 g_W2b[(size_t)4096 * 12288];  // W2' [N,3K]

__device__ __forceinline__ void bsplit(float x, unsigned short& h, unsigned short& l) {
    __nv_bfloat16 hb = __float2bfloat16(x);
    float r = x - __bfloat162float(hb);
    __nv_bfloat16 lb = __float2bfloat16(r);
    h = __bfloat16_as_ushort(hb);
    l = __bfloat16_as_ushort(lb);
}

// ---------------- metric ----------------
__global__ void k_metric(const float* __restrict__ ws, const float* __restrict__ pos,
                         float* __restrict__ metric, int p)
{
    int t   = blockIdx.x;
    int tok = t % p;
    const float* base = ws + (size_t)t * CDIM;
    int d = threadIdx.x;
    float s = 0.f;
    if (pos) {
        const float* pb = pos + (size_t)tok * CDIM;
        #pragma unroll
        for (int h = 0; h < HEADS; ++h) s += base[h * DDIM + d] + pb[h * DDIM + d];
    } else {
        #pragma unroll
        for (int h = 0; h < HEADS; ++h) s += base[h * DDIM + d];
    }
    float m = s * (1.f / 16.f);
    __shared__ float red[64];
    red[d] = m * m;
    __syncthreads();
    for (int off = 32; off > 0; off >>= 1) {
        if (d < off) red[d] += red[d + off];
        __syncthreads();
    }
    float nrm = sqrtf(red[0]);
    metric[(size_t)t * DDIM + d] = m / nrm;
}

// ---------------- fused scores + row argmax ----------------
__global__ __launch_bounds__(256) void k_argmax(const float* __restrict__ metric,
        float* __restrict__ nodemax, int* __restrict__ nodeidx, int n, int p)
{
    __shared__ float As[32][65];
    __shared__ float Bs[128][65];
    __shared__ float rv[32][33];
    __shared__ int   ri[32][33];

    int b     = blockIdx.y;
    int ibase = blockIdx.x * 32;
    const float* M = metric + (size_t)b * p * DDIM;
    int tid = threadIdx.x;
    int tx  = tid & 7;
    int ty  = tid >> 3;

    for (int idx = tid; idx < 32 * 64; idx += 256) {
        int r = idx >> 6, c = idx & 63;
        int ig = ibase + r;
        As[r][c] = (ig < n) ? M[(size_t)(2 * ig) * DDIM + c] : 0.f;
    }

    float runv = -1e30f;
    int   runj = 0;

    int ntiles = (n + 127) >> 7;
    for (int jt = 0; jt < ntiles; ++jt) {
        int jbase = jt << 7;
        __syncthreads();
        for (int idx = tid; idx < 128 * 64; idx += 256) {
            int r = idx >> 6, c = idx & 63;
            int jg = jbase + r;
            Bs[r][c] = (jg < n) ? M[(size_t)(2 * jg + 1) * DDIM + c] : 0.f;
        }
        __syncthreads();

        float acc[4][4];
        #pragma unroll
        for (int ii = 0; ii < 4; ii++)
            #pragma unroll
            for (int jj = 0; jj < 4; jj++) acc[ii][jj] = 0.f;

        #pragma unroll 8
        for (int k = 0; k < 64; k++) {
            float a0 = As[4 * tx + 0][k], a1 = As[4 * tx + 1][k];
            float a2 = As[4 * tx + 2][k], a3 = As[4 * tx + 3][k];
            float b0 = Bs[4 * ty + 0][k], b1 = Bs[4 * ty + 1][k];
            float b2 = Bs[4 * ty + 2][k], b3 = Bs[4 * ty + 3][k];
            acc[0][0] += a0 * b0; acc[0][1] += a0 * b1; acc[0][2] += a0 * b2; acc[0][3] += a0 * b3;
            acc[1][0] += a1 * b0; acc[1][1] += a1 * b1; acc[1][2] += a1 * b2; acc[1][3] += a1 * b3;
            acc[2][0] += a2 * b0; acc[2][1] += a2 * b1; acc[2][2] += a2 * b2; acc[2][3] += a2 * b3;
            acc[3][0] += a3 * b0; acc[3][1] += a3 * b1; acc[3][2] += a3 * b2; acc[3][3] += a3 * b3;
        }

        #pragma unroll
        for (int ii = 0; ii < 4; ii++) {
            float bv = -1e30f; int bj = -1;
            #pragma unroll
            for (int jj = 0; jj < 4; jj++) {
                int jg = jbase + 4 * ty + jj;
                if (jg < n && acc[ii][jj] > bv) { bv = acc[ii][jj]; bj = jg; }
            }
            rv[4 * tx + ii][ty] = bv;
            ri[4 * tx + ii][ty] = bj;
        }
        __syncthreads();
        if (tid < 32) {
            for (int t2 = 0; t2 < 32; ++t2) {
                float v = rv[tid][t2];
                if (v > runv) { runv = v; runj = ri[tid][t2]; }
            }
        }
    }
    if (tid < 32) {
        int ig = ibase + tid;
        if (ig < n) {
            nodemax[b * NMAX + ig] = runv;
            nodeidx[b * NMAX + ig] = runj;
        }
    }
}

// ---------------- rounds 1-5 merge ----------------
__global__ void k_dst_init(const float* __restrict__ ws, const float* __restrict__ pos,
        const float* __restrict__ szin, float* __restrict__ wsout, float* __restrict__ szout,
        int n, int p)
{
    int blk = blockIdx.x;
    int b = blk / n, j = blk % n;
    const float4* src = (const float4*)(ws + ((size_t)b * p + 2 * j + 1) * CDIM);
    float4* dst = (float4*)(wsout + ((size_t)b * n + j) * CDIM);
    int c = threadIdx.x;
    float4 v = src[c];
    if (pos) {
        const float4* pb = (const float4*)(pos + (size_t)(2 * j + 1) * CDIM);
        float4 pv = pb[c];
        v.x += pv.x; v.y += pv.y; v.z += pv.z; v.w += pv.w;
    }
    dst[c] = v;
    if (threadIdx.x == 0) szout[b * n + j] = szin ? szin[b * p + 2 * j + 1] : 1.f;
}

__global__ void k_scatter(const float* __restrict__ ws, const float* __restrict__ pos,
        const float* __restrict__ szin, const int* __restrict__ nodeidx,
        float* __restrict__ wsout, float* __restrict__ szout, int n, int p)
{
    int blk = blockIdx.x;
    int b = blk / n, i = blk % n;
    int j = nodeidx[b * NMAX + i];
    const float* src = ws + ((size_t)b * p + 2 * i) * CDIM;
    float* dst = wsout + ((size_t)b * n + j) * CDIM;
    if (pos) {
        const float* pb = pos + (size_t)(2 * i) * CDIM;
        for (int c = threadIdx.x; c < CDIM; c += 256) atomicAdd(dst + c, src[c] + pb[c]);
    } else {
        for (int c = threadIdx.x; c < CDIM; c += 256) atomicAdd(dst + c, src[c]);
    }
    if (threadIdx.x == 0) atomicAdd(szout + b * n + j, szin ? szin[b * p + 2 * i] : 1.f);
}

// ---------------- round 6 ----------------
__global__ void k_sort6(const float* __restrict__ nodemax, int* __restrict__ edge)
{
    if (threadIdx.x != 0) return;
    int b = blockIdx.x;
    float v[72]; int id[72];
    for (int i = 0; i < 72; i++) { v[i] = nodemax[b * NMAX + i]; id[i] = i; }
    for (int a = 1; a < 72; a++) {
        float kv = v[a]; int ki = id[a]; int c = a - 1;
        while (c >= 0 && v[c] < kv) { v[c + 1] = v[c]; id[c + 1] = id[c]; --c; }
        v[c + 1] = kv; id[c + 1] = ki;
    }
    for (int i = 0; i < 72; i++) edge[b * 72 + i] = id[i];
}

__global__ void k_round6(const float* __restrict__ ws, const float* __restrict__ sz,
        const int* __restrict__ nodeidx, const int* __restrict__ edge,
        float* __restrict__ wsout, float* __restrict__ szout)
{
    const int p = 144, r = 16, u = 56;
    int b = blockIdx.y, t = blockIdx.x;
    const float* wsb = ws + (size_t)b * p * CDIM;
    float* outp = wsout + ((size_t)b * 128 + t) * CDIM;
    if (t < u) {
        int e = edge[b * 72 + r + t];
        const float* src = wsb + (size_t)(2 * e) * CDIM;
        for (int c = threadIdx.x; c < CDIM; c += 256) outp[c] = src[c];
        if (threadIdx.x == 0) szout[b * 128 + t] = sz[b * p + 2 * e];
    } else {
        int j = t - u;
        __shared__ int msrc[16];
        __shared__ int mcount;
        if (threadIdx.x == 0) {
            int cnt = 0;
            float ssum = sz[b * p + 2 * j + 1];
            for (int s = 0; s < r; s++) {
                int e = edge[b * 72 + s];
                if (nodeidx[b * NMAX + e] == j) { msrc[cnt++] = 2 * e; ssum += sz[b * p + 2 * e]; }
            }
            mcount = cnt;
            szout[b * 128 + t] = ssum;
        }
        __syncthreads();
        const float* base = wsb + (size_t)(2 * j + 1) * CDIM;
        int cnt = mcount;
        for (int c = threadIdx.x; c < CDIM; c += 256) {
            float v = base[c];
            for (int q = 0; q < cnt; q++) v += wsb[(size_t)msrc[q] * CDIM + c];
            outp[c] = v;
        }
    }
}

// ---------------- conversions ----------------
__global__ void k_convA(const float* __restrict__ ws, const float* __restrict__ sz,
                        __nv_bfloat16* __restrict__ out)
{
    int idx = blockIdx.x * 256 + threadIdx.x;
    int m = idx >> 10, c = idx & 1023;
    float v = ws[idx] / sz[m];
    unsigned short h, l;
    bsplit(v, h, l);
    __nv_bfloat16* row = out + (size_t)m * 3072;
    row[c]        = __ushort_as_bfloat16(h);
    row[c + 1024] = __ushort_as_bfloat16(l);
    row[c + 2048] = __ushort_as_bfloat16(h);
}

// W (K,N) fp32 -> B' (N, 3K) bf16 [hi | hi | lo], transposed
__global__ void k_convW(const float* __restrict__ W, __nv_bfloat16* __restrict__ Bp,
                        int K, int N)
{
    __shared__ float tile[32][33];
    int n0 = blockIdx.x * 32, k0 = blockIdx.y * 32;
    int tx = threadIdx.x & 31, ty = threadIdx.x >> 5;
    #pragma unroll
    for (int i = 0; i < 4; i++)
        tile[ty + 8 * i][tx] = W[(size_t)(k0 + ty + 8 * i) * N + n0 + tx];
    __syncthreads();
    size_t s3K = (size_t)3 * K;
    #pragma unroll
    for (int i = 0; i < 4; i++) {
        float v = tile[tx][ty + 8 * i];
        unsigned short h, l;
        bsplit(v, h, l);
        __nv_bfloat16* row = Bp + (size_t)(n0 + ty + 8 * i) * s3K + k0 + tx;
        row[0]     = __ushort_as_bfloat16(h);
        row[K]     = __ushort_as_bfloat16(h);
        row[2 * K] = __ushort_as_bfloat16(l);
    }
}

// ---------------- warp-MMA bf16 GEMM: D(128x128 tile) = A'(MxK') @ B'(NxK')^T ----------------
// 8 warps (2x4), warp tile 64x32, BK=32, 2-stage cp.async pipeline.
// EPI=1: v = gelu(acc + bias) -> bf16 split into outS (row stride 12288, +0/+4096/+8192)
// EPI=0: v = acc + bias -> fp32 outF (row stride 4096)
#define SMPAD 40   // padded row stride in elements (80B): conflict-free ldmatrix

template<int EPI>
__global__ __launch_bounds__(256) void k_mma(
    const __nv_bfloat16* __restrict__ A, int lda,
    const __nv_bfloat16* __restrict__ B, int ldb,
    const float* __restrict__ bias,
    float* __restrict__ outF, __nv_bfloat16* __restrict__ outS, int K)
{
    __shared__ __align__(16) __nv_bfloat16 sA[2][128 * SMPAD];
    __shared__ __align__(16) __nv_bfloat16 sB[2][128 * SMPAD];

    int tid = threadIdx.x;
    int wid = tid >> 5, lane = tid & 31;
    int wm = wid >> 2, wn = wid & 3;           // warp grid 2x4
    int m0 = blockIdx.y * 128, n0 = blockIdx.x * 128;

    uint32_t saA = smem_u32(sA);
    uint32_t saB = smem_u32(sB);
    const uint32_t BUFB = 128 * SMPAD * 2;     // bytes per buffer

    float acc[4][4][4];
    #pragma unroll
    for (int i = 0; i < 4; i++)
        #pragma unroll
        for (int j = 0; j < 4; j++)
            #pragma unroll
            for (int q = 0; q < 4; q++) acc[i][j][q] = 0.f;

    int lrow = tid >> 2;          // 0..63
    int lseg = tid & 3;           // 0..3 (16B segments of 32-col row)
    uint32_t soff0 = (uint32_t)(lrow * SMPAD + lseg * 8) * 2;
    uint32_t soff1 = (uint32_t)((lrow + 64) * SMPAD + lseg * 8) * 2;

    const __nv_bfloat16* Abase = A + (size_t)(m0 + lrow) * lda + lseg * 8;
    const __nv_bfloat16* Bbase = B + (size_t)(n0 + lrow) * ldb + lseg * 8;
    size_t astep64 = (size_t)64 * lda;
    size_t bstep64 = (size_t)64 * ldb;

    int ntile = K >> 5;

    // prologue: tile 0
    {
        CP_ASYNC(saA + soff0, Abase);
        CP_ASYNC(saA + soff1, Abase + astep64);
        CP_ASYNC(saB + soff0, Bbase);
        CP_ASYNC(saB + soff1, Bbase + bstep64);
        CP_COMMIT();
    }

    for (int it = 0; it < ntile; it++) {
        int buf = it & 1;
        if (it + 1 < ntile) {
            int nb = buf ^ 1;
            const __nv_bfloat16* Ap = Abase + (size_t)(it + 1) * 32;
            const __nv_bfloat16* Bp = Bbase + (size_t)(it + 1) * 32;
            CP_ASYNC(saA + nb * BUFB + soff0, Ap);
            CP_ASYNC(saA + nb * BUFB + soff1, Ap + astep64);
            CP_ASYNC(saB + nb * BUFB + soff0, Bp);
            CP_ASYNC(saB + nb * BUFB + soff1, Bp + bstep64);
            CP_COMMIT();
            CP_WAIT(1);
        } else {
            CP_WAIT(0);
        }
        __syncthreads();

        uint32_t bufA = saA + buf * BUFB;
        uint32_t bufB2 = saB + buf * BUFB;
        #pragma unroll
        for (int ks = 0; ks < 2; ks++) {
            uint32_t a[4][4], b[2][4];
            int c = ks * 16 + (lane >> 4) * 8;
            #pragma unroll
            for (int mt = 0; mt < 4; mt++) {
                int r = wm * 64 + mt * 16 + (lane & 15);
                ldsm4(a[mt], bufA + (uint32_t)(r * SMPAD + c) * 2);
            }
            #pragma unroll
            for (int nt2 = 0; nt2 < 2; nt2++) {
                int r = wn * 32 + nt2 * 16 + (lane & 15);
                ldsm4(b[nt2], bufB2 + (uint32_t)(r * SMPAD + c) * 2);
            }
            #pragma unroll
            for (int mt = 0; mt < 4; mt++)
                #pragma unroll
                for (int nt = 0; nt < 4; nt++)
                    mma_bf16(acc[mt][nt], a[mt], b[nt >> 1][nt & 1], b[nt >> 1][(nt & 1) + 2]);
        }
        __syncthreads();
    }

    // epilogue
    int g = lane >> 2, tg = lane & 3;
    #pragma unroll
    for (int mt = 0; mt < 4; mt++) {
        #pragma unroll
        for (int half = 0; half < 2; half++) {
            int m = m0 + wm * 64 + mt * 16 + g + half * 8;
            #pragma unroll
            for (int nt = 0; nt < 4; nt++) {
                int col = n0 + wn * 32 + nt * 8 + tg * 2;
                float2 bb = *(const float2*)(bias + col);
                float v0 = acc[mt][nt][half * 2 + 0] + bb.x;
                float v1 = acc[mt][nt][half * 2 + 1] + bb.y;
                if (EPI == 1) {
                    v0 = 0.5f * v0 * (1.f + erff(v0 * 0.70710678118654752f));
                    v1 = 0.5f * v1 * (1.f + erff(v1 * 0.70710678118654752f));
                    unsigned short h0, l0, h1, l1;
                    bsplit(v0, h0, l0);
                    bsplit(v1, h1, l1);
                    uint32_t hp = (uint32_t)h0 | ((uint32_t)h1 << 16);
                    uint32_t lp = (uint32_t)l0 | ((uint32_t)l1 << 16);
                    __nv_bfloat16* rowp = outS + (size_t)m * 12288;
                    *(uint32_t*)(rowp + col)        = hp;
                    *(uint32_t*)(rowp + col + 4096) = lp;
                    *(uint32_t*)(rowp + col + 8192) = hp;
                } else {
                    float2 o; o.x = v0; o.y = v1;
                    *(float2*)(outF + (size_t)m * 4096 + col) = o;
                }
            }
        }
    }
}

// ---------------- launcher ----------------
extern "C" void kernel_launch(void* const* d_in, const int* in_sizes, int n_in,
                              void* d_out, int out_size)
{
    const float* x   = (const float*)d_in[0];
    const float* pos = (const float*)d_in[1];
    const float* W1  = (const float*)d_in[2];
    const float* b1  = (const float*)d_in[3];
    const float* W2  = (const float*)d_in[4];
    const float* b2  = (const float*)d_in[5];
    float* out = (float*)d_out;

    float *bufA, *bufB, *szA, *szB, *metric, *nmax;
    int *nidx, *edge;
    __nv_bfloat16 *A1, *A2, *W1b, *W2b;
    cudaGetSymbolAddress((void**)&bufA,   g_bufA);
    cudaGetSymbolAddress((void**)&bufB,   g_bufB);
    cudaGetSymbolAddress((void**)&szA,    g_sizeA);
    cudaGetSymbolAddress((void**)&szB,    g_sizeB);
    cudaGetSymbolAddress((void**)&metric, g_metric);
    cudaGetSymbolAddress((void**)&nmax,   g_nodemax);
    cudaGetSymbolAddress((void**)&nidx,   g_nodeidx);
    cudaGetSymbolAddress((void**)&edge,   g_edge);
    cudaGetSymbolAddress((void**)&A1,     g_A1);
    cudaGetSymbolAddress((void**)&A2,     g_A2);
    cudaGetSymbolAddress((void**)&W1b,    g_W1b);
    cudaGetSymbolAddress((void**)&W2b,    g_W2b);

    // weight conversions (independent of merge results)
    k_convW<<<dim3(4096 / 32, 1024 / 32), 256>>>(W1, W1b, 1024, 4096);
    k_convW<<<dim3(4096 / 32, 4096 / 32), 256>>>(W2, W2b, 4096, 4096);

    // Round 1: p=4608, n=r=2304
    k_metric<<<BATCH * 4608, 64>>>(x, pos, metric, 4608);
    k_argmax<<<dim3(72, BATCH), 256>>>(metric, nmax, nidx, 2304, 4608);
    k_dst_init<<<BATCH * 2304, 256>>>(x, pos, nullptr, bufB, szB, 2304, 4608);
    k_scatter<<<BATCH * 2304, 256>>>(x, pos, nullptr, nidx, bufB, szB, 2304, 4608);

    // Round 2
    k_metric<<<BATCH * 2304, 64>>>(bufB, nullptr, metric, 2304);
    k_argmax<<<dim3(36, BATCH), 256>>>(metric, nmax, nidx, 1152, 2304);
    k_dst_init<<<BATCH * 1152, 256>>>(bufB, nullptr, szB, bufA, szA, 1152, 2304);
    k_scatter<<<BATCH * 1152, 256>>>(bufB, nullptr, szB, nidx, bufA, szA, 1152, 2304);

    // Round 3
    k_metric<<<BATCH * 1152, 64>>>(bufA, nullptr, metric, 1152);
    k_argmax<<<dim3(18, BATCH), 256>>>(metric, nmax, nidx, 576, 1152);
    k_dst_init<<<BATCH * 576, 256>>>(bufA, nullptr, szA, bufB, szB, 576, 1152);
    k_scatter<<<BATCH * 576, 256>>>(bufA, nullptr, szA, nidx, bufB, szB, 576, 1152);

    // Round 4
    k_metric<<<BATCH * 576, 64>>>(bufB, nullptr, metric, 576);
    k_argmax<<<dim3(9, BATCH), 256>>>(metric, nmax, nidx, 288, 576);
    k_dst_init<<<BATCH * 288, 256>>>(bufB, nullptr, szB, bufA, szA, 288, 576);
    k_scatter<<<BATCH * 288, 256>>>(bufB, nullptr, szB, nidx, bufA, szA, 288, 576);

    // Round 5
    k_metric<<<BATCH * 288, 64>>>(bufA, nullptr, metric, 288);
    k_argmax<<<dim3(5, BATCH), 256>>>(metric, nmax, nidx, 144, 288);
    k_dst_init<<<BATCH * 144, 256>>>(bufA, nullptr, szA, bufB, szB, 144, 288);
    k_scatter<<<BATCH * 144, 256>>>(bufA, nullptr, szA, nidx, bufB, szB, 144, 288);

    // Round 6
    k_metric<<<BATCH * 144, 64>>>(bufB, nullptr, metric, 144);
    k_argmax<<<dim3(3, BATCH), 256>>>(metric, nmax, nidx, 72, 144);
    k_sort6<<<BATCH, 32>>>(nmax, edge);
    k_round6<<<dim3(128, BATCH), 256>>>(bufB, szB, nidx, edge, bufA, szA);

    // A conversion for GEMM1 (1024 tokens x 1024, /size, bf16x3 split)
    k_convA<<<4096, 256>>>(bufA, szA, A1);

    // GEMM1: gelu((A/sz)@W1+b1) -> bf16 split directly into A2
    k_mma<1><<<dim3(32, 8), 256>>>(A1, 3072, W1b, 3072, b1, nullptr, A2, 3072);
    // GEMM2: A2@W2+b2 -> out fp32
    k_mma<0><<<dim3(32, 8), 256>>>(A2, 12288, W2b, 12288, b2, out, nullptr, 12288);
}